// round 8
// baseline (speedup 1.0000x reference)
#include <cuda_runtime.h>

// DirichletLoss: ball query (r=0.15, K=32 nearest within radius) + neighbor
// feature variance, mean over all B*N queries, *0.5.
//
// 2-kernel pipeline (graph-capturable, scratch in __device__ globals):
//   k_build : per-batch block — smem histogram, multi-warp shfl scan,
//             counting-sort into float4(x,y,z,f) cell-major; global offsets
//   k_main  : warp-per-query, single pass. Packed keys
//             uint32 = (d2 bits & ~0xFFF) | batch-local index. Selection
//             state = 32 UNORDERED slots (one per lane); first chunk fills
//             all slots free; later candidates replace the current max
//             (reduce_max doubles as the admission cutoff). Radius test is
//             folded into the key compare via EMPTY = key(R2)+1.
//             Block partial -> last-block deterministic reduction -> out.
//
// All candidate ranges are clamped so every loop terminates even if the
// offset table were corrupt (bugs become wrong answers, not hangs).

#define FULLMASK 0xFFFFFFFFu

constexpr int   B    = 8;
constexpr int   N    = 4096;
constexpr int   BN   = B * N;
constexpr int   GD   = 7;            // cells per axis (cell = r = 0.15)
constexpr int   NC   = GD * GD * GD; // 343 cells per batch
constexpr int   TOTC = B * NC;
constexpr int   NBLK = BN / 8;       // k_main blocks (8 warps each)
constexpr float R2       = 0.15f * 0.15f;
constexpr float INV_CELL = 1.0f / 0.15f;
constexpr float BIGF     = 3.0e38f;
constexpr unsigned SENT  = 0xFFFFFFFFu;

__device__ int      g_off[TOTC + 1];
__device__ float4   g_pts[BN];       // (x,y,z,f) sorted by global cell id
__device__ float    g_var[NBLK];     // per-block partial sums
__device__ unsigned g_done;          // last-block ticket

__device__ __forceinline__ int cell1(float x) {
    int c = (int)(x * INV_CELL);
    c = c < 0 ? 0 : c;
    return c > GD - 1 ? GD - 1 : c;
}

// One block per batch: histogram -> multi-warp scan -> scatter.
__global__ void __launch_bounds__(1024) k_build(const float* __restrict__ pos,
                                                const float* __restrict__ f) {
    __shared__ int cnt[NC];
    __shared__ int sc [NC];          // inclusive per-warp scan
    __shared__ int wt [11], wb[11];  // warp totals / bases
    __shared__ int cur[NC];          // fill cursors (exclusive offsets)
    int b = blockIdx.x, t = threadIdx.x;
    int base = b * N;

    if (b == 0 && t == 0) g_done = 0;          // reset reduction ticket
    for (int i = t; i < NC; i += 1024) cnt[i] = 0;
    __syncthreads();

    float mx[4], my[4], mz[4], mf[4];
    int   mc[4];
    #pragma unroll
    for (int k = 0; k < 4; k++) {
        int gi = base + t + k * 1024;
        float x = pos[3 * gi], y = pos[3 * gi + 1], z = pos[3 * gi + 2];
        mx[k] = x; my[k] = y; mz[k] = z; mf[k] = f[gi];
        int c = (cell1(z) * GD + cell1(y)) * GD + cell1(x);
        mc[k] = c;
        atomicAdd(&cnt[c], 1);
    }
    __syncthreads();

    // 11 warps scan 32 cells each (352 >= NC=343).
    if (t < 352) {
        int w = t >> 5, l = t & 31;
        int x = (t < NC) ? cnt[t] : 0;
        int v = x;
        #pragma unroll
        for (int d = 1; d < 32; d <<= 1) {
            int u = __shfl_up_sync(FULLMASK, v, d);
            if (l >= d) v += u;
        }
        if (t < NC) sc[t] = v;                 // inclusive within warp
        if (l == 31) wt[w] = v;
    }
    __syncthreads();
    if (t < 32) {
        int v = (t < 11) ? wt[t] : 0;
        #pragma unroll
        for (int d = 1; d < 32; d <<= 1) {
            int u = __shfl_up_sync(FULLMASK, v, d);
            if (t >= d) v += u;
        }
        if (t < 11) wb[t] = v - wt[t];         // exclusive warp base
    }
    __syncthreads();
    if (t < NC) {
        int ex = sc[t] - cnt[t] + wb[t >> 5];  // exclusive offset
        cur[t] = ex;
        g_off[b * NC + t] = base + ex;
    }
    if (b == B - 1 && t == 0) g_off[TOTC] = BN;
    __syncthreads();

    #pragma unroll
    for (int k = 0; k < 4; k++) {
        int dst = base + atomicAdd(&cur[mc[k]], 1);
        if (dst >= 0 && dst < BN)
            g_pts[dst] = make_float4(mx[k], my[k], mz[k], mf[k]);
    }
}

// One warp per query; single pass; unordered-slot top-32; last block reduces.
__global__ void __launch_bounds__(256) k_main(float* __restrict__ out) {
    __shared__ float  swarp[8];
    __shared__ double sd[256];
    __shared__ bool   amLast;
    int lane = threadIdx.x & 31;
    int wid  = threadIdx.x >> 5;
    int q    = blockIdx.x * 8 + wid;

    float4 p = g_pts[q];
    int b    = q >> 12;               // sorted array stays batch-contiguous
    int base = b * N;
    int bNC  = b * NC;
    int cx = cell1(p.x), cy = cell1(p.y), cz = cell1(p.z);
    int xlo = cx > 0 ? cx - 1 : 0, xhi = cx < GD - 1 ? cx + 1 : GD - 1;

    // Key domain: pk = (d2 bits & ~0xFFF) | local index. cutR = largest
    // admissible key; EMPTY marks an unused slot; SENT marks OOB lanes.
    const unsigned cutR  = (__float_as_uint(R2) & 0xFFFFF000u) | 0xFFFu;
    const unsigned EMPTY = cutR + 1;

    unsigned kk = EMPTY;              // this lane's (unordered) kept slot
    unsigned curmax = EMPTY;          // warp max of kk == admission cutoff
    bool first = true;                // warp-uniform: free-fill flag

    // Center row first so the cutoff tightens early.
    const int dzs[3] = {0, -1, 1};
    const int dys[3] = {0, -1, 1};
    #pragma unroll
    for (int zi = 0; zi < 3; zi++) {
        int z = cz + dzs[zi];
        if (z < 0 || z >= GD) continue;
        #pragma unroll
        for (int yi = 0; yi < 3; yi++) {
            int y = cy + dys[yi];
            if (y < 0 || y >= GD) continue;
            int rb = bNC + (z * GD + y) * GD;
            int s0 = g_off[rb + xlo];
            int s1 = g_off[rb + xhi + 1];         // contiguous 3-cell row
            s0 = s0 < 0 ? 0 : s0;                 // termination guards
            s1 = s1 > BN ? BN : s1;
            for (int base0 = s0; base0 < s1; base0 += 32) {
                int j = base0 + lane;
                unsigned pk = SENT;
                if (j < s1) {
                    float4 c = g_pts[j];
                    float dx = c.x - p.x, dy = c.y - p.y, dz = c.z - p.z;
                    float d2 = fmaf(dx, dx, fmaf(dy, dy, dz * dz));
                    pk = (__float_as_uint(d2) & 0xFFFFF000u) |
                         (unsigned)(j - base);
                }
                if (first) {                       // free fill of all slots
                    kk = pk > cutR ? EMPTY : pk;
                    curmax = __reduce_max_sync(FULLMASK, kk);
                    first = false;
                    continue;
                }
                unsigned want = __ballot_sync(FULLMASK, pk < curmax);
                while (want) {
                    int src = __ffs(want) - 1;
                    want &= want - 1;
                    unsigned v = __shfl_sync(FULLMASK, pk, src);
                    if (v < curmax) {              // uniform re-check
                        unsigned mh = __ballot_sync(FULLMASK, kk == curmax);
                        if (lane == __ffs(mh) - 1) kk = v;   // evict one max
                        curmax = __reduce_max_sync(FULLMASK, kk);
                    }
                }
            }
        }
    }

    // Epilogue: each valid slot holds one selected neighbor.
    float acc = 0.0f;
    if (kk <= cutR) {
        int j = (int)(kk & 0xFFFu);
        float fj = g_pts[base + j].w;
        float df = p.w - fj;
        acc = df * df;
    }
    #pragma unroll
    for (int o = 16; o; o >>= 1) acc += __shfl_xor_sync(FULLMASK, acc, o);
    if (lane == 0) swarp[wid] = acc;
    __syncthreads();
    if (threadIdx.x == 0) {
        float s = 0.0f;
        #pragma unroll
        for (int w = 0; w < 8; w++) s += swarp[w];
        g_var[blockIdx.x] = s;
    }

    // ---- last-block deterministic reduction ----
    __threadfence();
    if (threadIdx.x == 0)
        amLast = (atomicAdd(&g_done, 1u) == (unsigned)(NBLK - 1));
    __syncthreads();
    if (amLast) {
        double a = 0.0;
        for (int i = threadIdx.x; i < NBLK; i += 256) a += (double)g_var[i];
        sd[threadIdx.x] = a;
        __syncthreads();
        for (int d = 128; d; d >>= 1) {
            if (threadIdx.x < d) sd[threadIdx.x] += sd[threadIdx.x + d];
            __syncthreads();
        }
        if (threadIdx.x == 0) out[0] = (float)(0.5 * sd[0] / (double)BN);
    }
}

extern "C" void kernel_launch(void* const* d_in, const int* in_sizes, int n_in,
                              void* d_out, int out_size) {
    const float* pos = (const float*)d_in[0];
    const float* f   = (const float*)d_in[1];
    if (n_in >= 2 && in_sizes[0] == BN && in_sizes[1] == 3 * BN) {
        const float* tmp = pos; pos = f; f = tmp;   // defensive input order
    }
    float* out = (float*)d_out;

    k_build<<<B, 1024>>>(pos, f);
    k_main<<<NBLK, 256>>>(out);
}

// round 11
// speedup vs baseline: 1.1283x; 1.1283x over previous
#include <cuda_runtime.h>

// DirichletLoss: ball query (r=0.15, K=32 nearest within radius) + neighbor
// feature variance, mean over all B*N queries, *0.5.
//
// 2-kernel pipeline (graph-capturable, scratch in __device__ globals):
//   k_build : per-batch block — smem histogram, multi-warp shfl scan,
//             counting-sort into float4(x,y,z,f) cell-major; global offsets
//   k_main  : warp-per-query, single pass, SORTED lane-distributed top-32 of
//             packed keys uint32 = (d2 bits & ~0xFFF) | batch-local index.
//             Radius test folded into the key cutoff; stencil row ranges
//             preloaded lane-parallel. Epilogue gathers f_j from kept keys.
//             Block partial -> last-block deterministic reduction -> out.
//
// All candidate ranges are clamped so every loop terminates even if the
// offset table were corrupt (bugs become wrong answers, not hangs).

#define FULLMASK 0xFFFFFFFFu

constexpr int   B    = 8;
constexpr int   N    = 4096;
constexpr int   BN   = B * N;
constexpr int   GD   = 7;            // cells per axis (cell = r = 0.15)
constexpr int   NC   = GD * GD * GD; // 343 cells per batch
constexpr int   TOTC = B * NC;
constexpr int   NBLK = BN / 8;       // k_main blocks (8 warps each)
constexpr float R2       = 0.15f * 0.15f;
constexpr float INV_CELL = 1.0f / 0.15f;
constexpr unsigned SENT  = 0xFFFFFFFFu;

__device__ int      g_off[TOTC + 1];
__device__ float4   g_pts[BN];       // (x,y,z,f) sorted by global cell id
__device__ float    g_var[NBLK];     // per-block partial sums
__device__ unsigned g_done;          // last-block ticket

__device__ __forceinline__ int cell1(float x) {
    int c = (int)(x * INV_CELL);
    c = c < 0 ? 0 : c;
    return c > GD - 1 ? GD - 1 : c;
}

// One block per batch: histogram -> multi-warp scan -> scatter.
__global__ void __launch_bounds__(1024) k_build(const float* __restrict__ pos,
                                                const float* __restrict__ f) {
    __shared__ int cnt[NC];
    __shared__ int sc [NC];          // inclusive per-warp scan
    __shared__ int wt [11], wb[11];  // warp totals / bases
    __shared__ int cur[NC];          // fill cursors (exclusive offsets)
    int b = blockIdx.x, t = threadIdx.x;
    int base = b * N;

    if (b == 0 && t == 0) g_done = 0;          // reset reduction ticket
    for (int i = t; i < NC; i += 1024) cnt[i] = 0;
    __syncthreads();

    float mx[4], my[4], mz[4], mf[4];
    int   mc[4];
    #pragma unroll
    for (int k = 0; k < 4; k++) {
        int gi = base + t + k * 1024;
        float x = pos[3 * gi], y = pos[3 * gi + 1], z = pos[3 * gi + 2];
        mx[k] = x; my[k] = y; mz[k] = z; mf[k] = f[gi];
        int c = (cell1(z) * GD + cell1(y)) * GD + cell1(x);
        mc[k] = c;
        atomicAdd(&cnt[c], 1);
    }
    __syncthreads();

    // 11 warps scan 32 cells each (352 >= NC=343).
    if (t < 352) {
        int w = t >> 5, l = t & 31;
        int x = (t < NC) ? cnt[t] : 0;
        int v = x;
        #pragma unroll
        for (int d = 1; d < 32; d <<= 1) {
            int u = __shfl_up_sync(FULLMASK, v, d);
            if (l >= d) v += u;
        }
        if (t < NC) sc[t] = v;                 // inclusive within warp
        if (l == 31) wt[w] = v;
    }
    __syncthreads();
    if (t < 32) {
        int v = (t < 11) ? wt[t] : 0;
        #pragma unroll
        for (int d = 1; d < 32; d <<= 1) {
            int u = __shfl_up_sync(FULLMASK, v, d);
            if (t >= d) v += u;
        }
        if (t < 11) wb[t] = v - wt[t];         // exclusive warp base
    }
    __syncthreads();
    if (t < NC) {
        int ex = sc[t] - cnt[t] + wb[t >> 5];  // exclusive offset
        cur[t] = ex;
        g_off[b * NC + t] = base + ex;
    }
    if (b == B - 1 && t == 0) g_off[TOTC] = BN;
    __syncthreads();

    #pragma unroll
    for (int k = 0; k < 4; k++) {
        int dst = base + atomicAdd(&cur[mc[k]], 1);
        if (dst >= 0 && dst < BN)
            g_pts[dst] = make_float4(mx[k], my[k], mz[k], mf[k]);
    }
}

// One warp per query; sorted top-32 packed keys; last block reduces.
__global__ void __launch_bounds__(256) k_main(float* __restrict__ out) {
    __shared__ float  swarp[8];
    __shared__ double sd[256];
    __shared__ bool   amLast;
    int lane = threadIdx.x & 31;
    int wid  = threadIdx.x >> 5;
    int q    = blockIdx.x * 8 + wid;

    float4 p = g_pts[q];
    int b    = q >> 12;               // sorted array stays batch-contiguous
    int base = b * N;
    const float4* pbase = g_pts + base;
    int cx = cell1(p.x), cy = cell1(p.y), cz = cell1(p.z);
    int xlo = cx > 0 ? cx - 1 : 0, xhi = cx < GD - 1 ? cx + 1 : GD - 1;

    // Key domain: pk = (d2 bits & ~0xFFF) | local index (12 bits).
    // cutR  = largest admissible key (radius test folded into compare).
    const unsigned cutR  = (__float_as_uint(R2) & 0xFFFFF000u) | 0xFFFu;
    const unsigned EMPTY = cutR + 1;

    // Lane-parallel preload of the 9 stencil row ranges (batch-local,
    // clamped). Row order: center (dz=0,dy=0) first so the cutoff
    // tightens early.
    int rs0 = 0, rs1 = 0;
    {
        const signed char DZ[9] = {0, 0, 0, -1, -1, -1, 1, 1, 1};
        const signed char DY[9] = {0, -1, 1, 0, -1, 1, 0, -1, 1};
        if (lane < 9) {
            int z = cz + DZ[lane], y = cy + DY[lane];
            if (z >= 0 && z < GD && y >= 0 && y < GD) {
                int rb = b * NC + (z * GD + y) * GD;
                int a0 = g_off[rb + xlo] - base;
                int a1 = g_off[rb + xhi + 1] - base;   // contiguous 3 cells
                a0 = a0 < 0 ? 0 : a0;                  // termination guards
                a1 = a1 > N ? N : a1;
                rs0 = a0;
                rs1 = a1 < a0 ? a0 : a1;
            }
        }
    }

    unsigned kk = SENT;               // lane-sorted ascending packed keys
    unsigned cutoffC = EMPTY;         // min(lane31 key, EMPTY)

    #pragma unroll 1
    for (int r = 0; r < 9; r++) {
        int l0 = __shfl_sync(FULLMASK, rs0, r);
        int l1 = __shfl_sync(FULLMASK, rs1, r);
        for (int c0 = l0; c0 < l1; c0 += 32) {
            int l = c0 + lane;
            unsigned pk = SENT;
            if (l < l1) {
                float4 c = pbase[l];
                float dx = c.x - p.x, dy = c.y - p.y, dz = c.z - p.z;
                float d2 = fmaf(dx, dx, fmaf(dy, dy, dz * dz));
                pk = (__float_as_uint(d2) & 0xFFFFF000u) | (unsigned)l;
            }
            unsigned want = __ballot_sync(FULLMASK, pk < cutoffC);
            if (want) {
                do {
                    int src = __ffs(want) - 1;
                    want &= want - 1;
                    unsigned v  = __shfl_sync(FULLMASK, pk, src);
                    unsigned pd = __shfl_up_sync(FULLMASK, kk, 1);
                    if (lane == 0) pd = 0u;
                    if (kk > v) kk = pd > v ? pd : v;   // sorted insert
                } while (want);
                unsigned k31 = __shfl_sync(FULLMASK, kk, 31);
                cutoffC = k31 < EMPTY ? k31 : EMPTY;
            }
        }
    }

    // Epilogue: each lane holds one selected neighbor (or none).
    float acc = 0.0f;
    if (kk <= cutR) {
        int l = (int)(kk & 0xFFFu);
        float fj = pbase[l].w;
        float df = p.w - fj;
        acc = df * df;
    }
    #pragma unroll
    for (int o = 16; o; o >>= 1) acc += __shfl_xor_sync(FULLMASK, acc, o);
    if (lane == 0) swarp[wid] = acc;
    __syncthreads();
    if (threadIdx.x == 0) {
        float s = 0.0f;
        #pragma unroll
        for (int w = 0; w < 8; w++) s += swarp[w];
        g_var[blockIdx.x] = s;
    }

    // ---- last-block deterministic reduction ----
    __threadfence();
    if (threadIdx.x == 0)
        amLast = (atomicAdd(&g_done, 1u) == (unsigned)(NBLK - 1));
    __syncthreads();
    if (amLast) {
        double a = 0.0;
        for (int i = threadIdx.x; i < NBLK; i += 256) a += (double)g_var[i];
        sd[threadIdx.x] = a;
        __syncthreads();
        for (int d = 128; d; d >>= 1) {
            if (threadIdx.x < d) sd[threadIdx.x] += sd[threadIdx.x + d];
            __syncthreads();
        }
        if (threadIdx.x == 0) out[0] = (float)(0.5 * sd[0] / (double)BN);
    }
}

extern "C" void kernel_launch(void* const* d_in, const int* in_sizes, int n_in,
                              void* d_out, int out_size) {
    const float* pos = (const float*)d_in[0];
    const float* f   = (const float*)d_in[1];
    if (n_in >= 2 && in_sizes[0] == BN && in_sizes[1] == 3 * BN) {
        const float* tmp = pos; pos = f; f = tmp;   // defensive input order
    }
    float* out = (float*)d_out;

    k_build<<<B, 1024>>>(pos, f);
    k_main<<<NBLK, 256>>>(out);
}